// round 5
// baseline (speedup 1.0000x reference)
#include <cuda_runtime.h>
#include <cuda_bf16.h>
#include <cstdint>

// ---------------- problem constants ----------------
#define N_IMG   32
#define C_IN    256
#define HW      64
#define K_OUT   256
#define X_ELEMS (N_IMG * C_IN * HW * HW)          // 33554432
#define W_ELEMS (K_OUT * C_IN * 9)                // 589824
#define NWBLK   (W_ELEMS / 16)                    // 36864

// ---------------- scratch (e4m3 quantized tensors) ----------------
__device__ uint8_t g_xq[X_ELEMS];                 // NHWC fp8: ((n*64+h)*64+w)*256 + c
__device__ uint8_t g_wq2[9 * K_OUT * C_IN];       // [rs][k][c] fp8

// ---------------- fp8 convert helpers ----------------
__device__ __forceinline__ uint32_t pack_e4m3_x4(float c0, float c1, float c2, float c3) {
    uint16_t lo, hi;
    asm volatile("cvt.rn.satfinite.e4m3x2.f32 %0, %1, %2;" : "=h"(lo) : "f"(c1), "f"(c0));
    asm volatile("cvt.rn.satfinite.e4m3x2.f32 %0, %1, %2;" : "=h"(hi) : "f"(c3), "f"(c2));
    return (uint32_t)lo | ((uint32_t)hi << 16);
}
__device__ __forceinline__ uint8_t f32_to_e4m3(float v) {
    uint16_t r;
    asm volatile("cvt.rn.satfinite.e4m3x2.f32 %0, %1, %2;" : "=h"(r) : "f"(0.0f), "f"(v));
    return (uint8_t)(r & 0xFF);
}

// ---------------- fake-quant core: returns dequantized fp32 ----------------
__device__ __forceinline__ void quant16f(const float* __restrict__ v,
                                         float* __restrict__ q) {
    float amax = 0.0f;
#pragma unroll
    for (int i = 0; i < 16; ++i) amax = fmaxf(amax, fabsf(v[i]));
    float scale = 1.0f;
    if (amax > 0.0f) {
        float y = fmaxf(amax, 1e-30f) / 6.0f;
        int e;
        float m = frexpf(y, &e);                            // y = m*2^e, m in [0.5,1)
        scale = ldexpf(1.0f, (m == 0.5f) ? (e - 1) : e);    // exact ceil(log2 y)
    }
    float inv = 1.0f / scale;
#pragma unroll
    for (int i = 0; i < 16; ++i) {
        float u = v[i] * inv;
        float a = fabsf(u);
        float g;
        if      (a < 0.25f) g = 0.0f;
        else if (a < 0.75f) g = 0.5f;
        else if (a < 1.25f) g = 1.0f;
        else if (a < 1.75f) g = 1.5f;
        else if (a < 2.5f)  g = 2.0f;
        else if (a < 3.5f)  g = 3.0f;
        else if (a < 5.0f)  g = 4.0f;
        else                g = 6.0f;
        q[i] = copysignf(g, u) * scale;                     // exact in e4m3
    }
}

// ---------------- x quant -> NHWC fp8 ----------------
// grid (32,64)=(n,h), 256 threads. Thread: channel quad (4c) x one 16-pixel block.
__global__ void __launch_bounds__(256)
quant_x_nhwc(const float* __restrict__ x, uint8_t* __restrict__ xq) {
    __shared__ uint32_t buf[64][68];   // [pixel][channel-quad], pitch 68 (16B-aligned rows)
    const int n  = blockIdx.x;
    const int h  = blockIdx.y;
    const int t  = threadIdx.x;
    const int cq = t & 63;             // channels 4cq..4cq+3
    const int wb = t >> 6;             // pixel block 0..3

    float q[4][16];
#pragma unroll
    for (int j = 0; j < 4; ++j) {
        const float4* src = reinterpret_cast<const float4*>(
            x + (((size_t)n * C_IN + 4 * cq + j) * HW + h) * HW + wb * 16);
        float v[16];
#pragma unroll
        for (int i = 0; i < 4; ++i) {
            float4 a = src[i];
            v[i * 4 + 0] = a.x; v[i * 4 + 1] = a.y; v[i * 4 + 2] = a.z; v[i * 4 + 3] = a.w;
        }
        quant16f(v, q[j]);
    }
#pragma unroll
    for (int p = 0; p < 16; ++p)
        buf[wb * 16 + p][cq] = pack_e4m3_x4(q[0][p], q[1][p], q[2][p], q[3][p]);
    __syncthreads();

    uint8_t* orow = xq + (((size_t)n * HW + h) * HW) * C_IN;
#pragma unroll
    for (int i = 0; i < 4; ++i) {
        int idx = t + 256 * i;          // 0..1023
        int p   = idx >> 4;             // pixel
        int qd  = idx & 15;             // 16B quad within 256B pixel row
        uint4 val = *reinterpret_cast<const uint4*>(&buf[p][qd * 4]);
        *reinterpret_cast<uint4*>(orow + (size_t)p * C_IN + qd * 16) = val;
    }
}

// ---------------- w quant + repack -> [rs][k][c] fp8 ----------------
__global__ void quant_w_repack(const float* __restrict__ w,
                               uint8_t* __restrict__ wq2) {
    int b = blockIdx.x * blockDim.x + threadIdx.x;
    if (b >= NWBLK) return;
    const float4* src = reinterpret_cast<const float4*>(w) + (size_t)b * 4;
    float4 t0 = src[0], t1 = src[1], t2 = src[2], t3 = src[3];
    float v[16] = {t0.x, t0.y, t0.z, t0.w, t1.x, t1.y, t1.z, t1.w,
                   t2.x, t2.y, t2.z, t2.w, t3.x, t3.y, t3.z, t3.w};
    float q[16];
    quant16f(v, q);
#pragma unroll
    for (int i = 0; i < 16; ++i) {
        int f  = b * 16 + i;                // OIHW flat: ((k*256 + c)*9 + rs)
        int k  = f / 2304;
        int r2 = f - k * 2304;
        int c  = r2 / 9;
        int rs = r2 - c * 9;
        wq2[((size_t)rs * K_OUT + k) * C_IN + c] = f32_to_e4m3(q[i]);
    }
}

// ---------------- PTX helpers ----------------
__device__ __forceinline__ void cp_async16(void* dst, const void* src, bool pred) {
    uint32_t d = (uint32_t)__cvta_generic_to_shared(dst);
    int sz = pred ? 16 : 0;
    asm volatile("cp.async.cg.shared.global [%0], [%1], 16, %2;\n"
                 :: "r"(d), "l"(src), "r"(sz));
}
__device__ __forceinline__ void cp_commit() {
    asm volatile("cp.async.commit_group;\n");
}
template <int N>
__device__ __forceinline__ void cp_wait() {
    asm volatile("cp.async.wait_group %0;\n" :: "n"(N));
}
__device__ __forceinline__ void ldsm_x4(uint32_t addr, uint32_t& r0, uint32_t& r1,
                                        uint32_t& r2, uint32_t& r3) {
    asm volatile("ldmatrix.sync.aligned.m8n8.x4.shared.b16 {%0,%1,%2,%3}, [%4];"
                 : "=r"(r0), "=r"(r1), "=r"(r2), "=r"(r3) : "r"(addr));
}
__device__ __forceinline__ void ldsm_x2(uint32_t addr, uint32_t& r0, uint32_t& r1) {
    asm volatile("ldmatrix.sync.aligned.m8n8.x2.shared.b16 {%0,%1}, [%2];"
                 : "=r"(r0), "=r"(r1) : "r"(addr));
}
// fp8 e4m3 mma, K=32. Fragments == bf16 k16 fragments with b16 -> fp8 pair.
__device__ __forceinline__ void mma16832(float* d, const uint32_t* a,
                                         uint32_t b0, uint32_t b1) {
    asm volatile("mma.sync.aligned.m16n8k32.row.col.f32.e4m3.e4m3.f32 "
                 "{%0,%1,%2,%3}, {%4,%5,%6,%7}, {%8,%9}, {%0,%1,%2,%3};"
                 : "+f"(d[0]), "+f"(d[1]), "+f"(d[2]), "+f"(d[3])
                 : "r"(a[0]), "r"(a[1]), "r"(a[2]), "r"(a[3]), "r"(b0), "r"(b1));
}

// ---------------- conv: implicit GEMM, fp8 mma, 2 CTA/SM ----------------
// CTA: 64 kout x (4 rows x 64 cols). 4 warps = 4 output rows; warp = 64k x 64pix.
// smem rows: 32 fp8 channels padded to 48B -> conflict-free ldmatrix.
#define CPADB 48
#define XS_BYTES (6 * 66 * CPADB)       // 19008
#define WS_BYTES (9 * 64 * CPADB)       // 27648
#define SBUF_B   (XS_BYTES + WS_BYTES)  // 46656
#define SMEM_BYTES (2 * SBUF_B)         // 93312

__device__ __forceinline__ void stage_chunk(char* xsb, char* wsb,
                                            const uint8_t* __restrict__ xq,
                                            const uint8_t* __restrict__ wq2,
                                            int n, int h0, int k0, int cc, int t) {
    const uint8_t* xn = xq + (size_t)n * HW * HW * C_IN;
    // X: 6 rows x 64 cols x 32c = 768 x 16B
#pragma unroll
    for (int i = 0; i < 6; ++i) {
        int idx  = t + 128 * i;
        int half = idx & 1;
        int rc   = idx >> 1;
        int row  = rc >> 6;            // 0..5
        int col  = rc & 63;
        int gr   = h0 - 1 + row;
        bool ok  = (unsigned)gr < (unsigned)HW;
        int grs  = ok ? gr : 0;
        cp_async16(xsb + (row * 66 + 1 + col) * CPADB + half * 16,
                   xn + ((size_t)grs * HW + col) * C_IN + cc + half * 16, ok);
    }
    // W: 9 rs x 64 k x 32c = 1152 x 16B
#pragma unroll
    for (int i = 0; i < 9; ++i) {
        int idx  = t + 128 * i;
        int half = idx & 1;
        int rk   = idx >> 1;
        int rs   = rk >> 6;            // 0..8
        int k    = rk & 63;
        cp_async16(wsb + (rs * 64 + k) * CPADB + half * 16,
                   wq2 + ((size_t)rs * K_OUT + k0 + k) * C_IN + cc + half * 16, true);
    }
}

__global__ void __launch_bounds__(128, 2)
conv3x3_fp8(const uint8_t* __restrict__ xq,
            const uint8_t* __restrict__ wq2,
            float* __restrict__ out) {
    extern __shared__ char smem[];

    const int n  = blockIdx.x;
    const int ht = blockIdx.y;         // 0..15
    const int kt = blockIdx.z;         // 0..3
    const int h0 = ht * 4;
    const int k0 = kt * 64;

    const int t    = threadIdx.x;
    const int lane = t & 31;
    const int wn   = t >> 5;           // output row 0..3

    // zero left/right halo columns in both buffers: 2buf x 6row x 2col x 3quads = 72
    if (t < 72) {
        int buf  = t / 36;
        int rem  = t % 36;
        int row  = rem / 6;
        int j    = rem % 6;
        int col  = (j < 3) ? 0 : 65;
        int quad = j % 3;
        *reinterpret_cast<uint4*>(smem + buf * SBUF_B + (row * 66 + col) * CPADB +
                                  quad * 16) = make_uint4(0, 0, 0, 0);
    }

    // ldmatrix per-lane byte offsets
    const int a_off = (lane & 15) * CPADB + (lane >> 4) * 16;       // A x4
    const int b_off = (lane & 7) * CPADB + ((lane >> 3) & 1) * 16;  // B x2

    float acc[4][8][4];
#pragma unroll
    for (int i = 0; i < 4; ++i)
#pragma unroll
        for (int j = 0; j < 8; ++j)
#pragma unroll
            for (int v = 0; v < 4; ++v) acc[i][j][v] = 0.0f;

    stage_chunk(smem, smem + XS_BYTES, xq, wq2, n, h0, k0, 0, t);
    cp_commit();

    const uint32_t smem_u = (uint32_t)__cvta_generic_to_shared(smem);

#pragma unroll 1
    for (int it = 0; it < 8; ++it) {
        int cur = it & 1;
        if (it + 1 < 8) {
            int nxt = cur ^ 1;
            stage_chunk(smem + nxt * SBUF_B, smem + nxt * SBUF_B + XS_BYTES,
                        xq, wq2, n, h0, k0, (it + 1) * 32, t);
            cp_commit();
            cp_wait<1>();
        } else {
            cp_wait<0>();
        }
        __syncthreads();

        const uint32_t xs_b = smem_u + cur * SBUF_B;
        const uint32_t ws_b = xs_b + XS_BYTES;

#pragma unroll
        for (int r = 0; r < 3; ++r) {
#pragma unroll
            for (int s = 0; s < 3; ++s) {
                const int rs = r * 3 + s;
                uint32_t a[4][4];
#pragma unroll
                for (int i = 0; i < 4; ++i)
                    ldsm_x4(ws_b + (rs * 64 + i * 16) * CPADB + a_off,
                            a[i][0], a[i][1], a[i][2], a[i][3]);
#pragma unroll
                for (int jn = 0; jn < 8; ++jn) {
                    uint32_t b0, b1;
                    ldsm_x2(xs_b + ((wn + r) * 66 + jn * 8 + s) * CPADB + b_off, b0, b1);
#pragma unroll
                    for (int i = 0; i < 4; ++i)
                        mma16832(acc[i][jn], a[i], b0, b1);
                }
            }
        }
        __syncthreads();
    }

    // epilogue: lane g=lane/4 holds cols 2t,2t+1 at rows g, g+8
    const int g  = lane >> 2;
    const int tc = lane & 3;
    const size_t kbase = (size_t)n * K_OUT + k0;
#pragma unroll
    for (int i = 0; i < 4; ++i) {
#pragma unroll
        for (int jn = 0; jn < 8; ++jn) {
            size_t o0 = ((kbase + i * 16 + g) * HW + h0 + wn) * HW + jn * 8 + 2 * tc;
            size_t o1 = o0 + (size_t)8 * HW * HW;
            *reinterpret_cast<float2*>(out + o0) = make_float2(acc[i][jn][0], acc[i][jn][1]);
            *reinterpret_cast<float2*>(out + o1) = make_float2(acc[i][jn][2], acc[i][jn][3]);
        }
    }
}

// ---------------- launch ----------------
extern "C" void kernel_launch(void* const* d_in, const int* in_sizes, int n_in,
                              void* d_out, int out_size) {
    const float* x = (const float*)d_in[0];
    const float* w = (const float*)d_in[1];
    if (in_sizes[0] != X_ELEMS) {
        x = (const float*)d_in[1];
        w = (const float*)d_in[0];
    }

    void* xq_ptr = nullptr;
    void* wq_ptr = nullptr;
    cudaGetSymbolAddress(&xq_ptr, g_xq);
    cudaGetSymbolAddress(&wq_ptr, g_wq2);
    uint8_t* xq  = (uint8_t*)xq_ptr;
    uint8_t* wq2 = (uint8_t*)wq_ptr;

    cudaFuncSetAttribute(conv3x3_fp8,
                         cudaFuncAttributeMaxDynamicSharedMemorySize, SMEM_BYTES);

    quant_x_nhwc<<<dim3(N_IMG, HW), 256>>>(x, xq);
    quant_w_repack<<<(NWBLK + 255) / 256, 256>>>(w, wq2);

    dim3 grid(N_IMG, 16, 4);
    conv3x3_fp8<<<grid, 128, SMEM_BYTES>>>(xq, wq2, (float*)d_out);
}

// round 6
// speedup vs baseline: 1.0064x; 1.0064x over previous
#include <cuda_runtime.h>
#include <cuda_bf16.h>
#include <cstdint>

// ---------------- problem constants ----------------
#define N_IMG   32
#define C_IN    256
#define HW      64
#define K_OUT   256
#define X_ELEMS (N_IMG * C_IN * HW * HW)          // 33554432
#define W_ELEMS (K_OUT * C_IN * 9)                // 589824
#define NWBLK   (W_ELEMS / 16)                    // 36864

// ---------------- scratch (e4m3 quantized tensors) ----------------
__device__ uint8_t g_xq[X_ELEMS];                 // NHWC fp8
__device__ uint8_t g_wq2[9 * K_OUT * C_IN];       // [rs][k][c] fp8

// ---------------- fp8 convert helpers ----------------
__device__ __forceinline__ uint16_t pack_e4m3_x2(float lo, float hi) {
    uint16_t r;
    asm volatile("cvt.rn.satfinite.e4m3x2.f32 %0, %1, %2;" : "=h"(r) : "f"(hi), "f"(lo));
    return r;
}
__device__ __forceinline__ uint8_t f32_to_e4m3(float v) {
    uint16_t r;
    asm volatile("cvt.rn.satfinite.e4m3x2.f32 %0, %1, %2;" : "=h"(r) : "f"(0.0f), "f"(v));
    return (uint8_t)(r & 0xFF);
}

// ---------------- fake-quant core: returns dequantized fp32 ----------------
__device__ __forceinline__ void quant16f(const float* __restrict__ v,
                                         float* __restrict__ q) {
    float amax = 0.0f;
#pragma unroll
    for (int i = 0; i < 16; ++i) amax = fmaxf(amax, fabsf(v[i]));
    float scale = 1.0f;
    if (amax > 0.0f) {
        float y = fmaxf(amax, 1e-30f) / 6.0f;
        int e;
        float m = frexpf(y, &e);                            // y = m*2^e, m in [0.5,1)
        scale = ldexpf(1.0f, (m == 0.5f) ? (e - 1) : e);    // exact ceil(log2 y)
    }
    float inv = 1.0f / scale;
#pragma unroll
    for (int i = 0; i < 16; ++i) {
        float u = v[i] * inv;
        float a = fabsf(u);
        float g;
        if      (a < 0.25f) g = 0.0f;
        else if (a < 0.75f) g = 0.5f;
        else if (a < 1.25f) g = 1.0f;
        else if (a < 1.75f) g = 1.5f;
        else if (a < 2.5f)  g = 2.0f;
        else if (a < 3.5f)  g = 3.0f;
        else if (a < 5.0f)  g = 4.0f;
        else                g = 6.0f;
        q[i] = copysignf(g, u) * scale;                     // exact in e4m3
    }
}

// ---------------- x quant -> NHWC fp8 (2 channels / thread) ----------------
// grid (32,64)=(n,h), 256 threads.
__global__ void __launch_bounds__(256)
quant_x_nhwc(const float* __restrict__ x, uint8_t* __restrict__ xq) {
    __shared__ uint16_t buf[64][136];   // [pixel][cpair], pitch 272B (16B-mult)
    const int n = blockIdx.x;
    const int h = blockIdx.y;
    const int t = threadIdx.x;
    const int cp  = t & 127;            // channel pair: c = 2cp, 2cp+1
    const int wb0 = t >> 7;

#pragma unroll
    for (int wbi = 0; wbi < 2; ++wbi) {
        int wb = wb0 + wbi * 2;         // pixel block 0..3
        const float* base = x + (((size_t)n * C_IN + 2 * cp) * HW + h) * HW + wb * 16;
        const float4* p0 = reinterpret_cast<const float4*>(base);
        const float4* p1 = reinterpret_cast<const float4*>(base + (size_t)HW * HW);
        float v0[16], v1[16];
#pragma unroll
        for (int i = 0; i < 4; ++i) {
            float4 a = p0[i];
            v0[i * 4 + 0] = a.x; v0[i * 4 + 1] = a.y; v0[i * 4 + 2] = a.z; v0[i * 4 + 3] = a.w;
            float4 b = p1[i];
            v1[i * 4 + 0] = b.x; v1[i * 4 + 1] = b.y; v1[i * 4 + 2] = b.z; v1[i * 4 + 3] = b.w;
        }
        float q0[16], q1[16];
        quant16f(v0, q0);
        quant16f(v1, q1);
#pragma unroll
        for (int j = 0; j < 16; ++j)
            buf[wb * 16 + j][cp] = pack_e4m3_x2(q0[j], q1[j]);
    }
    __syncthreads();

    uint8_t* orow = xq + (((size_t)n * HW + h) * HW) * C_IN;
#pragma unroll
    for (int i = 0; i < 4; ++i) {
        int idx = t + 256 * i;           // 0..1023
        int p   = idx >> 4;              // pixel
        int qd  = idx & 15;              // 16B quad within 256B pixel row
        uint4 val = *reinterpret_cast<const uint4*>(&buf[p][qd * 8]);
        *reinterpret_cast<uint4*>(orow + (size_t)p * C_IN + qd * 16) = val;
    }
}

// ---------------- w quant + repack -> [rs][k][c] fp8 ----------------
__global__ void quant_w_repack(const float* __restrict__ w,
                               uint8_t* __restrict__ wq2) {
    int b = blockIdx.x * blockDim.x + threadIdx.x;
    if (b >= NWBLK) return;
    const float4* src = reinterpret_cast<const float4*>(w) + (size_t)b * 4;
    float4 t0 = src[0], t1 = src[1], t2 = src[2], t3 = src[3];
    float v[16] = {t0.x, t0.y, t0.z, t0.w, t1.x, t1.y, t1.z, t1.w,
                   t2.x, t2.y, t2.z, t2.w, t3.x, t3.y, t3.z, t3.w};
    float q[16];
    quant16f(v, q);
#pragma unroll
    for (int i = 0; i < 16; ++i) {
        int f  = b * 16 + i;                // OIHW flat: ((k*256 + c)*9 + rs)
        int k  = f / 2304;
        int r2 = f - k * 2304;
        int c  = r2 / 9;
        int rs = r2 - c * 9;
        wq2[((size_t)rs * K_OUT + k) * C_IN + c] = f32_to_e4m3(q[i]);
    }
}

// ---------------- PTX helpers ----------------
__device__ __forceinline__ void cp_async16(void* dst, const void* src, bool pred) {
    uint32_t d = (uint32_t)__cvta_generic_to_shared(dst);
    int sz = pred ? 16 : 0;
    asm volatile("cp.async.cg.shared.global [%0], [%1], 16, %2;\n"
                 :: "r"(d), "l"(src), "r"(sz));
}
__device__ __forceinline__ void cp_commit() {
    asm volatile("cp.async.commit_group;\n");
}
template <int N>
__device__ __forceinline__ void cp_wait() {
    asm volatile("cp.async.wait_group %0;\n" :: "n"(N));
}
__device__ __forceinline__ void ldsm_x4(uint32_t addr, uint32_t& r0, uint32_t& r1,
                                        uint32_t& r2, uint32_t& r3) {
    asm volatile("ldmatrix.sync.aligned.m8n8.x4.shared.b16 {%0,%1,%2,%3}, [%4];"
                 : "=r"(r0), "=r"(r1), "=r"(r2), "=r"(r3) : "r"(addr));
}
__device__ __forceinline__ void ldsm_x2(uint32_t addr, uint32_t& r0, uint32_t& r1) {
    asm volatile("ldmatrix.sync.aligned.m8n8.x2.shared.b16 {%0,%1}, [%2];"
                 : "=r"(r0), "=r"(r1) : "r"(addr));
}
__device__ __forceinline__ void mma16832(float* d, const uint32_t* a,
                                         uint32_t b0, uint32_t b1) {
    asm volatile("mma.sync.aligned.m16n8k32.row.col.f32.e4m3.e4m3.f32 "
                 "{%0,%1,%2,%3}, {%4,%5,%6,%7}, {%8,%9}, {%0,%1,%2,%3};"
                 : "+f"(d[0]), "+f"(d[1]), "+f"(d[2]), "+f"(d[3])
                 : "r"(a[0]), "r"(a[1]), "r"(a[2]), "r"(a[3]), "r"(b0), "r"(b1));
}

// ---------------- conv: implicit GEMM, fp8 mma, 3-stage pipeline ----------------
// CTA: 128 kout x (4 rows x 64 cols). 8 warps: wm(2) x wn(4). Warp = 64k x 64pix.
// smem rows: 32 fp8 channels padded to 48B -> conflict-free ldmatrix.
#define CPADB 48
#define XS_BYTES (6 * 66 * CPADB)       // 19008
#define WS_BYTES (9 * 128 * CPADB)      // 55296
#define STAGE_B  (XS_BYTES + WS_BYTES)  // 74304
#define NSTAGE 3
#define SMEM_BYTES (NSTAGE * STAGE_B)   // 222912
#define NITER 8                          // 256 channels / 32 per chunk

__device__ __forceinline__ void stage_chunk(char* base,
                                            const uint8_t* __restrict__ xq,
                                            const uint8_t* __restrict__ wq2,
                                            int n, int h0, int k0, int cc, int t) {
    const uint8_t* xn = xq + (size_t)n * HW * HW * C_IN;
    // X: 6 rows x 64 cols x 32c = 768 x 16B
#pragma unroll
    for (int i = 0; i < 3; ++i) {
        int idx  = t + 256 * i;
        int half = idx & 1;
        int rc   = idx >> 1;
        int row  = rc >> 6;            // 0..5
        int col  = rc & 63;
        int gr   = h0 - 1 + row;
        bool ok  = (unsigned)gr < (unsigned)HW;
        int grs  = ok ? gr : 0;
        cp_async16(base + (row * 66 + 1 + col) * CPADB + half * 16,
                   xn + ((size_t)grs * HW + col) * C_IN + cc + half * 16, ok);
    }
    // W: 9 rs x 128 k x 32c = 2304 x 16B
#pragma unroll
    for (int i = 0; i < 9; ++i) {
        int idx  = t + 256 * i;
        int half = idx & 1;
        int rk   = idx >> 1;
        int rs   = rk >> 7;            // 0..8
        int k    = rk & 127;
        cp_async16(base + XS_BYTES + (rs * 128 + k) * CPADB + half * 16,
                   wq2 + ((size_t)rs * K_OUT + k0 + k) * C_IN + cc + half * 16, true);
    }
}

__global__ void __launch_bounds__(256, 1)
conv3x3_fp8(const uint8_t* __restrict__ xq,
            const uint8_t* __restrict__ wq2,
            float* __restrict__ out) {
    extern __shared__ char smem[];

    const int n  = blockIdx.x;
    const int ht = blockIdx.y;         // 0..15
    const int kt = blockIdx.z;         // 0..1
    const int h0 = ht * 4;
    const int k0 = kt * 128;

    const int t    = threadIdx.x;
    const int lane = t & 31;
    const int warp = t >> 5;
    const int wm   = warp & 1;         // k half (64 k)
    const int wn   = warp >> 1;        // output row 0..3

    // zero left/right halo columns in all 3 stages: 3 x 6row x 2col x 3quads = 108
    if (t < 108) {
        int stg  = t / 36;
        int rem  = t % 36;
        int row  = rem / 6;
        int j    = rem % 6;
        int col  = (j < 3) ? 0 : 65;
        int quad = j % 3;
        *reinterpret_cast<uint4*>(smem + stg * STAGE_B + (row * 66 + col) * CPADB +
                                  quad * 16) = make_uint4(0, 0, 0, 0);
    }
    __syncthreads();   // halo zeros visible before any compute

    // ldmatrix per-lane byte offsets
    const int a_off = (lane & 15) * CPADB + (lane >> 4) * 16;       // A x4
    const int b_off = (lane & 7) * CPADB + ((lane >> 3) & 1) * 16;  // B x2

    float acc[4][8][4];
#pragma unroll
    for (int i = 0; i < 4; ++i)
#pragma unroll
        for (int j = 0; j < 8; ++j)
#pragma unroll
            for (int v = 0; v < 4; ++v) acc[i][j][v] = 0.0f;

    // prologue: stages 0,1
    stage_chunk(smem + 0 * STAGE_B, xq, wq2, n, h0, k0, 0, t);
    cp_commit();
    stage_chunk(smem + 1 * STAGE_B, xq, wq2, n, h0, k0, 32, t);
    cp_commit();

    const uint32_t smem_u = (uint32_t)__cvta_generic_to_shared(smem);
    int cur = 0, nxt2 = 2;

#pragma unroll 1
    for (int it = 0; it < NITER; ++it) {
        if (it + 2 < NITER) cp_wait<1>(); else cp_wait<0>();
        __syncthreads();   // data ready + all warps done reading stage being overwritten

        if (it + 2 < NITER) {
            stage_chunk(smem + nxt2 * STAGE_B, xq, wq2, n, h0, k0, (it + 2) * 32, t);
            cp_commit();
        }

        const uint32_t xs_b = smem_u + cur * STAGE_B;
        const uint32_t ws_b = xs_b + XS_BYTES;

#pragma unroll
        for (int r = 0; r < 3; ++r) {
#pragma unroll
            for (int s = 0; s < 3; ++s) {
                const int rs = r * 3 + s;
                uint32_t a[4][4];
#pragma unroll
                for (int i = 0; i < 4; ++i)
                    ldsm_x4(ws_b + (rs * 128 + wm * 64 + i * 16) * CPADB + a_off,
                            a[i][0], a[i][1], a[i][2], a[i][3]);
#pragma unroll
                for (int jn = 0; jn < 8; ++jn) {
                    uint32_t b0, b1;
                    ldsm_x2(xs_b + ((wn + r) * 66 + jn * 8 + s) * CPADB + b_off, b0, b1);
#pragma unroll
                    for (int i = 0; i < 4; ++i)
                        mma16832(acc[i][jn], a[i], b0, b1);
                }
            }
        }
        cur = (cur + 1 == NSTAGE) ? 0 : cur + 1;
        nxt2 = (nxt2 + 1 == NSTAGE) ? 0 : nxt2 + 1;
    }

    // epilogue: lane g=lane/4 holds cols 2t,2t+1 at rows g, g+8
    const int g  = lane >> 2;
    const int tc = lane & 3;
    const size_t kbase = (size_t)n * K_OUT + k0 + wm * 64;
#pragma unroll
    for (int i = 0; i < 4; ++i) {
#pragma unroll
        for (int jn = 0; jn < 8; ++jn) {
            size_t o0 = ((kbase + i * 16 + g) * HW + h0 + wn) * HW + jn * 8 + 2 * tc;
            size_t o1 = o0 + (size_t)8 * HW * HW;
            *reinterpret_cast<float2*>(out + o0) = make_float2(acc[i][jn][0], acc[i][jn][1]);
            *reinterpret_cast<float2*>(out + o1) = make_float2(acc[i][jn][2], acc[i][jn][3]);
        }
    }
}

// ---------------- launch ----------------
extern "C" void kernel_launch(void* const* d_in, const int* in_sizes, int n_in,
                              void* d_out, int out_size) {
    const float* x = (const float*)d_in[0];
    const float* w = (const float*)d_in[1];
    if (in_sizes[0] != X_ELEMS) {
        x = (const float*)d_in[1];
        w = (const float*)d_in[0];
    }

    void* xq_ptr = nullptr;
    void* wq_ptr = nullptr;
    cudaGetSymbolAddress(&xq_ptr, g_xq);
    cudaGetSymbolAddress(&wq_ptr, g_wq2);
    uint8_t* xq  = (uint8_t*)xq_ptr;
    uint8_t* wq2 = (uint8_t*)wq_ptr;

    cudaFuncSetAttribute(conv3x3_fp8,
                         cudaFuncAttributeMaxDynamicSharedMemorySize, SMEM_BYTES);

    quant_x_nhwc<<<dim3(N_IMG, HW), 256>>>(x, xq);
    quant_w_repack<<<(NWBLK + 255) / 256, 256>>>(w, wq2);

    dim3 grid(N_IMG, 16, 2);
    conv3x3_fp8<<<grid, 256, SMEM_BYTES>>>(xq, wq2, (float*)d_out);
}

// round 7
// speedup vs baseline: 1.0082x; 1.0018x over previous
#include <cuda_runtime.h>
#include <cuda_bf16.h>
#include <cstdint>

// ---------------- problem constants ----------------
#define N_IMG   32
#define C_IN    256
#define HW      64
#define K_OUT   256
#define X_ELEMS (N_IMG * C_IN * HW * HW)          // 33554432
#define W_ELEMS (K_OUT * C_IN * 9)                // 589824
#define NWBLK   (W_ELEMS / 16)                    // 36864

// ---------------- scratch (e4m3 quantized tensors) ----------------
__device__ uint8_t g_xq[X_ELEMS];                 // NHWC fp8
__device__ uint8_t g_wq2[9 * K_OUT * C_IN];       // [rs][k][c] fp8

// ---------------- fp8 convert helpers ----------------
__device__ __forceinline__ uint16_t pack_e4m3_x2(float lo, float hi) {
    uint16_t r;
    asm volatile("cvt.rn.satfinite.e4m3x2.f32 %0, %1, %2;" : "=h"(r) : "f"(hi), "f"(lo));
    return r;
}
__device__ __forceinline__ uint8_t f32_to_e4m3(float v) {
    uint16_t r;
    asm volatile("cvt.rn.satfinite.e4m3x2.f32 %0, %1, %2;" : "=h"(r) : "f"(0.0f), "f"(v));
    return (uint8_t)(r & 0xFF);
}

// ---------------- fake-quant core: returns dequantized fp32 ----------------
__device__ __forceinline__ void quant16f(const float* __restrict__ v,
                                         float* __restrict__ q) {
    float amax = 0.0f;
#pragma unroll
    for (int i = 0; i < 16; ++i) amax = fmaxf(amax, fabsf(v[i]));
    float scale = 1.0f;
    if (amax > 0.0f) {
        float y = fmaxf(amax, 1e-30f) / 6.0f;
        int e;
        float m = frexpf(y, &e);                            // y = m*2^e, m in [0.5,1)
        scale = ldexpf(1.0f, (m == 0.5f) ? (e - 1) : e);    // exact ceil(log2 y)
    }
    float inv = 1.0f / scale;
#pragma unroll
    for (int i = 0; i < 16; ++i) {
        float u = v[i] * inv;
        float a = fabsf(u);
        float g;
        if      (a < 0.25f) g = 0.0f;
        else if (a < 0.75f) g = 0.5f;
        else if (a < 1.25f) g = 1.0f;
        else if (a < 1.75f) g = 1.5f;
        else if (a < 2.5f)  g = 2.0f;
        else if (a < 3.5f)  g = 3.0f;
        else if (a < 5.0f)  g = 4.0f;
        else                g = 6.0f;
        q[i] = copysignf(g, u) * scale;                     // exact in e4m3
    }
}

// ---------------- x quant -> NHWC fp8 (2 channels / thread) ----------------
// grid (32,64)=(n,h), 256 threads.
__global__ void __launch_bounds__(256)
quant_x_nhwc(const float* __restrict__ x, uint8_t* __restrict__ xq) {
    __shared__ uint16_t buf[64][136];   // [pixel][cpair], pitch 272B (16B-mult)
    const int n = blockIdx.x;
    const int h = blockIdx.y;
    const int t = threadIdx.x;
    const int cp  = t & 127;            // channel pair: c = 2cp, 2cp+1
    const int wb0 = t >> 7;

#pragma unroll
    for (int wbi = 0; wbi < 2; ++wbi) {
        int wb = wb0 + wbi * 2;         // pixel block 0..3
        const float* base = x + (((size_t)n * C_IN + 2 * cp) * HW + h) * HW + wb * 16;
        const float4* p0 = reinterpret_cast<const float4*>(base);
        const float4* p1 = reinterpret_cast<const float4*>(base + (size_t)HW * HW);
        float v0[16], v1[16];
#pragma unroll
        for (int i = 0; i < 4; ++i) {
            float4 a = p0[i];
            v0[i * 4 + 0] = a.x; v0[i * 4 + 1] = a.y; v0[i * 4 + 2] = a.z; v0[i * 4 + 3] = a.w;
            float4 b = p1[i];
            v1[i * 4 + 0] = b.x; v1[i * 4 + 1] = b.y; v1[i * 4 + 2] = b.z; v1[i * 4 + 3] = b.w;
        }
        float q0[16], q1[16];
        quant16f(v0, q0);
        quant16f(v1, q1);
#pragma unroll
        for (int j = 0; j < 16; ++j)
            buf[wb * 16 + j][cp] = pack_e4m3_x2(q0[j], q1[j]);
    }
    __syncthreads();

    uint8_t* orow = xq + (((size_t)n * HW + h) * HW) * C_IN;
#pragma unroll
    for (int i = 0; i < 4; ++i) {
        int idx = t + 256 * i;           // 0..1023
        int p   = idx >> 4;              // pixel
        int qd  = idx & 15;              // 16B quad within 256B pixel row
        uint4 val = *reinterpret_cast<const uint4*>(&buf[p][qd * 8]);
        *reinterpret_cast<uint4*>(orow + (size_t)p * C_IN + qd * 16) = val;
    }
}

// ---------------- w quant + repack -> [rs][k][c] fp8 ----------------
__global__ void quant_w_repack(const float* __restrict__ w,
                               uint8_t* __restrict__ wq2) {
    int b = blockIdx.x * blockDim.x + threadIdx.x;
    if (b >= NWBLK) return;
    const float4* src = reinterpret_cast<const float4*>(w) + (size_t)b * 4;
    float4 t0 = src[0], t1 = src[1], t2 = src[2], t3 = src[3];
    float v[16] = {t0.x, t0.y, t0.z, t0.w, t1.x, t1.y, t1.z, t1.w,
                   t2.x, t2.y, t2.z, t2.w, t3.x, t3.y, t3.z, t3.w};
    float q[16];
    quant16f(v, q);
#pragma unroll
    for (int i = 0; i < 16; ++i) {
        int f  = b * 16 + i;                // OIHW flat: ((k*256 + c)*9 + rs)
        int k  = f / 2304;
        int r2 = f - k * 2304;
        int c  = r2 / 9;
        int rs = r2 - c * 9;
        wq2[((size_t)rs * K_OUT + k) * C_IN + c] = f32_to_e4m3(q[i]);
    }
}

// ---------------- PTX helpers ----------------
__device__ __forceinline__ void cp_async16(void* dst, const void* src, bool pred) {
    uint32_t d = (uint32_t)__cvta_generic_to_shared(dst);
    int sz = pred ? 16 : 0;
    asm volatile("cp.async.cg.shared.global [%0], [%1], 16, %2;\n"
                 :: "r"(d), "l"(src), "r"(sz));
}
__device__ __forceinline__ void cp_commit() {
    asm volatile("cp.async.commit_group;\n");
}
template <int N>
__device__ __forceinline__ void cp_wait() {
    asm volatile("cp.async.wait_group %0;\n" :: "n"(N));
}
__device__ __forceinline__ void ldsm_x4(uint32_t addr, uint32_t& r0, uint32_t& r1,
                                        uint32_t& r2, uint32_t& r3) {
    asm volatile("ldmatrix.sync.aligned.m8n8.x4.shared.b16 {%0,%1,%2,%3}, [%4];"
                 : "=r"(r0), "=r"(r1), "=r"(r2), "=r"(r3) : "r"(addr));
}
__device__ __forceinline__ void ldsm_x2(uint32_t addr, uint32_t& r0, uint32_t& r1) {
    asm volatile("ldmatrix.sync.aligned.m8n8.x2.shared.b16 {%0,%1}, [%2];"
                 : "=r"(r0), "=r"(r1) : "r"(addr));
}
__device__ __forceinline__ void mma16832(float* d, const uint32_t* a,
                                         uint32_t b0, uint32_t b1) {
    asm volatile("mma.sync.aligned.m16n8k32.row.col.f32.e4m3.e4m3.f32 "
                 "{%0,%1,%2,%3}, {%4,%5,%6,%7}, {%8,%9}, {%0,%1,%2,%3};"
                 : "+f"(d[0]), "+f"(d[1]), "+f"(d[2]), "+f"(d[3])
                 : "r"(a[0]), "r"(a[1]), "r"(a[2]), "r"(a[3]), "r"(b0), "r"(b1));
}

// ---------------- conv: implicit GEMM, fp8 mma, 3-stage pipeline ----------------
// CTA: 128 kout x (4 rows x 64 cols). 8 warps: wm(2) x wn(4). Warp = 64k x 64pix.
// smem rows: 32 fp8 channels padded to 48B -> conflict-free ldmatrix.
#define CPADB 48
#define XS_BYTES (6 * 66 * CPADB)       // 19008
#define WS_BYTES (9 * 128 * CPADB)      // 55296
#define STAGE_B  (XS_BYTES + WS_BYTES)  // 74304
#define NSTAGE 3
#define SMEM_BYTES (NSTAGE * STAGE_B)   // 222912
#define NITER 8                          // 256 channels / 32 per chunk

__device__ __forceinline__ void stage_chunk(char* base,
                                            const uint8_t* __restrict__ xq,
                                            const uint8_t* __restrict__ wq2,
                                            int n, int h0, int k0, int cc, int t) {
    const uint8_t* xn = xq + (size_t)n * HW * HW * C_IN;
    // X: 6 rows x 64 cols x 32c = 768 x 16B
#pragma unroll
    for (int i = 0; i < 3; ++i) {
        int idx  = t + 256 * i;
        int half = idx & 1;
        int rc   = idx >> 1;
        int row  = rc >> 6;            // 0..5
        int col  = rc & 63;
        int gr   = h0 - 1 + row;
        bool ok  = (unsigned)gr < (unsigned)HW;
        int grs  = ok ? gr : 0;
        cp_async16(base + (row * 66 + 1 + col) * CPADB + half * 16,
                   xn + ((size_t)grs * HW + col) * C_IN + cc + half * 16, ok);
    }
    // W: 9 rs x 128 k x 32c = 2304 x 16B
#pragma unroll
    for (int i = 0; i < 9; ++i) {
        int idx  = t + 256 * i;
        int half = idx & 1;
        int rk   = idx >> 1;
        int rs   = rk >> 7;            // 0..8
        int k    = rk & 127;
        cp_async16(base + XS_BYTES + (rs * 128 + k) * CPADB + half * 16,
                   wq2 + ((size_t)rs * K_OUT + k0 + k) * C_IN + cc + half * 16, true);
    }
}

__global__ void __launch_bounds__(256, 1)
conv3x3_fp8(const uint8_t* __restrict__ xq,
            const uint8_t* __restrict__ wq2,
            float* __restrict__ out) {
    extern __shared__ char smem[];

    const int n  = blockIdx.x;
    const int ht = blockIdx.y;         // 0..15
    const int kt = blockIdx.z;         // 0..1
    const int h0 = ht * 4;
    const int k0 = kt * 128;

    const int t    = threadIdx.x;
    const int lane = t & 31;
    const int warp = t >> 5;
    const int wm   = warp & 1;         // k half (64 k)
    const int wn   = warp >> 1;        // output row 0..3

    // zero left/right halo columns in all 3 stages: 3 x 6row x 2col x 3quads = 108
    if (t < 108) {
        int stg  = t / 36;
        int rem  = t % 36;
        int row  = rem / 6;
        int j    = rem % 6;
        int col  = (j < 3) ? 0 : 65;
        int quad = j % 3;
        *reinterpret_cast<uint4*>(smem + stg * STAGE_B + (row * 66 + col) * CPADB +
                                  quad * 16) = make_uint4(0, 0, 0, 0);
    }
    __syncthreads();   // halo zeros visible before any compute

    // ldmatrix per-lane byte offsets
    const int a_off = (lane & 15) * CPADB + (lane >> 4) * 16;       // A x4
    const int b_off = (lane & 7) * CPADB + ((lane >> 3) & 1) * 16;  // B x2

    float acc[4][8][4];
#pragma unroll
    for (int i = 0; i < 4; ++i)
#pragma unroll
        for (int j = 0; j < 8; ++j)
#pragma unroll
            for (int v = 0; v < 4; ++v) acc[i][j][v] = 0.0f;

    // prologue: stages 0,1
    stage_chunk(smem + 0 * STAGE_B, xq, wq2, n, h0, k0, 0, t);
    cp_commit();
    stage_chunk(smem + 1 * STAGE_B, xq, wq2, n, h0, k0, 32, t);
    cp_commit();

    const uint32_t smem_u = (uint32_t)__cvta_generic_to_shared(smem);
    int cur = 0, nxt2 = 2;

#pragma unroll 1
    for (int it = 0; it < NITER; ++it) {
        if (it + 2 < NITER) cp_wait<1>(); else cp_wait<0>();
        __syncthreads();   // data ready + all warps done reading stage being overwritten

        if (it + 2 < NITER) {
            stage_chunk(smem + nxt2 * STAGE_B, xq, wq2, n, h0, k0, (it + 2) * 32, t);
            cp_commit();
        }

        const uint32_t xs_b = smem_u + cur * STAGE_B;
        const uint32_t ws_b = xs_b + XS_BYTES;

#pragma unroll
        for (int r = 0; r < 3; ++r) {
#pragma unroll
            for (int s = 0; s < 3; ++s) {
                const int rs = r * 3 + s;
                uint32_t a[4][4];
#pragma unroll
                for (int i = 0; i < 4; ++i)
                    ldsm_x4(ws_b + (rs * 128 + wm * 64 + i * 16) * CPADB + a_off,
                            a[i][0], a[i][1], a[i][2], a[i][3]);
#pragma unroll
                for (int jn = 0; jn < 8; ++jn) {
                    uint32_t b0, b1;
                    ldsm_x2(xs_b + ((wn + r) * 66 + jn * 8 + s) * CPADB + b_off, b0, b1);
#pragma unroll
                    for (int i = 0; i < 4; ++i)
                        mma16832(acc[i][jn], a[i], b0, b1);
                }
            }
        }
        cur = (cur + 1 == NSTAGE) ? 0 : cur + 1;
        nxt2 = (nxt2 + 1 == NSTAGE) ? 0 : nxt2 + 1;
    }

    // epilogue: lane g=lane/4 holds cols 2t,2t+1 at rows g, g+8
    const int g  = lane >> 2;
    const int tc = lane & 3;
    const size_t kbase = (size_t)n * K_OUT + k0 + wm * 64;
#pragma unroll
    for (int i = 0; i < 4; ++i) {
#pragma unroll
        for (int jn = 0; jn < 8; ++jn) {
            size_t o0 = ((kbase + i * 16 + g) * HW + h0 + wn) * HW + jn * 8 + 2 * tc;
            size_t o1 = o0 + (size_t)8 * HW * HW;
            *reinterpret_cast<float2*>(out + o0) = make_float2(acc[i][jn][0], acc[i][jn][1]);
            *reinterpret_cast<float2*>(out + o1) = make_float2(acc[i][jn][2], acc[i][jn][3]);
        }
    }
}

// ---------------- launch ----------------
extern "C" void kernel_launch(void* const* d_in, const int* in_sizes, int n_in,
                              void* d_out, int out_size) {
    const float* x = (const float*)d_in[0];
    const float* w = (const float*)d_in[1];
    if (in_sizes[0] != X_ELEMS) {
        x = (const float*)d_in[1];
        w = (const float*)d_in[0];
    }

    void* xq_ptr = nullptr;
    void* wq_ptr = nullptr;
    cudaGetSymbolAddress(&xq_ptr, g_xq);
    cudaGetSymbolAddress(&wq_ptr, g_wq2);
    uint8_t* xq  = (uint8_t*)xq_ptr;
    uint8_t* wq2 = (uint8_t*)wq_ptr;

    cudaFuncSetAttribute(conv3x3_fp8,
                         cudaFuncAttributeMaxDynamicSharedMemorySize, SMEM_BYTES);

    quant_x_nhwc<<<dim3(N_IMG, HW), 256>>>(x, xq);
    quant_w_repack<<<(NWBLK + 255) / 256, 256>>>(w, wq2);

    dim3 grid(N_IMG, 16, 2);
    conv3x3_fp8<<<grid, 256, SMEM_BYTES>>>(xq, wq2, (float*)d_out);
}